// round 9
// baseline (speedup 1.0000x reference)
#include <cuda_runtime.h>
#include <math.h>
#include <stdint.h>

#define NB 16
#define NL 2048
#define ND 512
#define NE 8
#define NH 8
#define NEH 64
#define NF 2048
#define LN_EPS 1e-5f

// ---------------- static device scratch (no allocations) ----------------
__device__ float g_srel [NB*NE];
__device__ float g_mu   [NB];
__device__ float g_rs   [NB];
__device__ float g_qh   [NB*NE*ND];
__device__ float g_qdot [NB*NEH];
__device__ float g_qt   [NB*NEH*ND];
__device__ float g_probs[NB*NEH*NL];     // scores -> probs in place (8MB)
__device__ float g_ctxp [4][NB*NEH*ND];  // L-split partials (deterministic)
__device__ float g_attn [NB*NE*ND];
__device__ float g_x    [NB*NE*ND];
__device__ float g_xo   [NB*NE*ND];
__device__ float g_h1   [NE*NB*NF];      // h1 as [e][b][f]
__device__ float g_part [1048576];       // K-split GEMM partials (4MB)

// ---------------- tf32 helpers ----------------
__device__ __forceinline__ float tf32r(float x){
    uint32_t t;
    asm("cvt.rna.tf32.f32 %0, %1;" : "=r"(t) : "f"(x));
    return __uint_as_float(t);
}
__device__ __forceinline__ void mma_tf32(float* acc, uint32_t a0, uint32_t a1,
                                         uint32_t a2, uint32_t a3,
                                         uint32_t b0, uint32_t b1){
    asm volatile(
        "mma.sync.aligned.m16n8k8.row.col.f32.tf32.tf32.f32 "
        "{%0,%1,%2,%3}, {%4,%5,%6,%7}, {%8,%9}, {%0,%1,%2,%3};"
        : "+f"(acc[0]), "+f"(acc[1]), "+f"(acc[2]), "+f"(acc[3])
        : "r"(a0), "r"(a1), "r"(a2), "r"(a3), "r"(b0), "r"(b1));
}

// ---------------- block reductions (blockDim.x == 256) ----------------
__device__ __forceinline__ float blkSum(float v){
    __shared__ float sb[8];
    int lane = threadIdx.x & 31, w = threadIdx.x >> 5;
    #pragma unroll
    for(int o=16;o;o>>=1) v += __shfl_xor_sync(0xffffffffu, v, o);
    __syncthreads();
    if(lane==0) sb[w] = v;
    __syncthreads();
    float r = 0.f;
    #pragma unroll
    for(int i=0;i<8;i++) r += sb[i];
    __syncthreads();
    return r;
}
__device__ __forceinline__ float blkMax(float v){
    __shared__ float sb[8];
    int lane = threadIdx.x & 31, w = threadIdx.x >> 5;
    #pragma unroll
    for(int o=16;o;o>>=1) v = fmaxf(v, __shfl_xor_sync(0xffffffffu, v, o));
    __syncthreads();
    if(lane==0) sb[w] = v;
    __syncthreads();
    float r = sb[0];
    #pragma unroll
    for(int i=1;i<8;i++) r = fmaxf(r, sb[i]);
    __syncthreads();
    return r;
}

// ---------------- 1: per-b LN stats of query ----------------
__global__ void k_gstat(const float* __restrict__ q){
    int b = blockIdx.x, tid = threadIdx.x;
    float s=0.f, ss=0.f;
    for(int d=tid; d<ND; d+=256){ float v = q[b*ND+d]; s+=v; ss+=v*v; }
    float S  = blkSum(s);
    float SS = blkSum(ss);
    if(tid==0){
        float mu = S*(1.f/ND);
        g_mu[b] = mu;
        g_rs[b] = rsqrtf(SS*(1.f/ND) - mu*mu + LN_EPS);
    }
}

// ---------------- generic K-split skinny GEMM ----------------
// part[z][(b*NE+e)*N + k] = sum_{d in chunk z} in'[b,e,d] * W[e,d,k]
// LNQ: in' = (in[b,d]-mu[b])*rs[b]*lng[e,d]+lnb[e,d]  (in = query, strideE=0)
template<int N, int D, int DS, int LNQ>
__global__ void k_gemm(const float* __restrict__ W, const float* __restrict__ in,
                       int strideB, int strideE,
                       const float* __restrict__ lng, const float* __restrict__ lnb){
    constexpr int DC = D/DS;
    int e = blockIdx.y, z = blockIdx.z, tid = threadIdx.x;
    __shared__ float xs[NB][DC+1];
    for(int i=tid; i<NB*DC; i+=256){
        int b = i/DC, d = i - b*DC;
        float v = in[(size_t)b*strideB + (size_t)e*strideE + z*DC + d];
        if(LNQ){
            int gd = e*ND + z*DC + d;
            v = (v - g_mu[b])*g_rs[b]*lng[gd] + lnb[gd];
        }
        xs[b][d] = v;
    }
    __syncthreads();
    int c4 = tid & 63, g = tid >> 6;
    int k = blockIdx.x*256 + c4*4;
    int b0 = g*4;
    float4 a0 = {0,0,0,0}, a1 = {0,0,0,0}, a2 = {0,0,0,0}, a3 = {0,0,0,0};
    const float4* wp = (const float4*)(W + ((size_t)e*D + (size_t)z*DC)*N + k);
    #pragma unroll 8
    for(int d=0; d<DC; d++){
        float4 w = wp[(size_t)d*(N/4)];
        float x0 = xs[b0][d], x1 = xs[b0+1][d], x2 = xs[b0+2][d], x3 = xs[b0+3][d];
        a0.x += w.x*x0; a0.y += w.y*x0; a0.z += w.z*x0; a0.w += w.w*x0;
        a1.x += w.x*x1; a1.y += w.y*x1; a1.z += w.z*x1; a1.w += w.w*x1;
        a2.x += w.x*x2; a2.y += w.y*x2; a2.z += w.z*x2; a2.w += w.w*x2;
        a3.x += w.x*x3; a3.y += w.y*x3; a3.z += w.z*x3; a3.w += w.w*x3;
    }
    float* po = g_part + (size_t)z*(NB*NE*N);
    *(float4*)&po[((size_t)(b0+0)*NE+e)*N + k] = a0;
    *(float4*)&po[((size_t)(b0+1)*NE+e)*N + k] = a1;
    *(float4*)&po[((size_t)(b0+2)*NE+e)*N + k] = a2;
    *(float4*)&po[((size_t)(b0+3)*NE+e)*N + k] = a3;
}

// ---------------- templated partial reduce + epilogue (float4, full unroll) ----
// ADDM: 0 none, 2 +addp[idx];  H1: [e][b][k] layout;  GELU: exact gelu
template<int ZC, int N, int NLOG, int ADDM, int H1, int GELU>
__global__ void k_redT(const float* __restrict__ bias, const float* __restrict__ addp,
                       float* __restrict__ dst){
    int i4 = blockIdx.x*256 + threadIdx.x;
    int base = i4*4;
    constexpr int span4 = NB*NE*N/4;
    float4 s = {0,0,0,0};
    const float4* gp = (const float4*)g_part;
    #pragma unroll
    for(int z=0; z<ZC; z++){
        float4 v = gp[(size_t)z*span4 + i4];
        s.x += v.x; s.y += v.y; s.z += v.z; s.w += v.w;
    }
    int k = base & (N-1);
    int r = base >> NLOG;
    int b = r >> 3, e = r & 7;
    float4 bb = *(const float4*)&bias[e*N + k];
    s.x += bb.x; s.y += bb.y; s.z += bb.z; s.w += bb.w;
    if(ADDM==2){
        float4 q = ((const float4*)addp)[i4];
        s.x += q.x; s.y += q.y; s.z += q.z; s.w += q.w;
    }
    if(GELU){
        s.x = 0.5f*s.x*(1.f + erff(s.x*0.70710678118654752f));
        s.y = 0.5f*s.y*(1.f + erff(s.y*0.70710678118654752f));
        s.z = 0.5f*s.z*(1.f + erff(s.z*0.70710678118654752f));
        s.w = 0.5f*s.w*(1.f + erff(s.w*0.70710678118654752f));
    }
    if(H1) *(float4*)&dst[((size_t)(e*NB + b))*N + k] = s;
    else   ((float4*)dst)[i4] = s;
}

// ---- Wo reduce + residual + out-LN fused (2 rows per block) ----
// x = query + part-sum + bo  -> g_x;  xo = LN(x)*g+b -> g_xo
__global__ void k_redln(const float* __restrict__ bias, const float* __restrict__ query,
                        const float* __restrict__ gw, const float* __restrict__ bw){
    int tid = threadIdx.x;
    int i4 = blockIdx.x*256 + tid;
    int base = i4*4;
    constexpr int span4 = NB*NE*ND/4;
    float4 s = {0,0,0,0};
    const float4* gp = (const float4*)g_part;
    #pragma unroll
    for(int z=0; z<8; z++){
        float4 v = gp[(size_t)z*span4 + i4];
        s.x += v.x; s.y += v.y; s.z += v.z; s.w += v.w;
    }
    int k = base & (ND-1);
    int r = base >> 9;
    int b = r >> 3, e = r & 7;
    float4 bb = *(const float4*)&bias[e*ND + k];
    float4 qq = *(const float4*)&query[b*ND + k];
    s.x += bb.x + qq.x; s.y += bb.y + qq.y; s.z += bb.z + qq.z; s.w += bb.w + qq.w;
    *(float4*)&g_x[base] = s;
    // block-local LN: 2 rows per block (threads 0-127 row0, 128-255 row1)
    float ps = s.x + s.y + s.z + s.w;
    float pss = s.x*s.x + s.y*s.y + s.z*s.z + s.w*s.w;
    int lane = tid & 31, w = tid >> 5, rowl = tid >> 7;
    #pragma unroll
    for(int o=16;o;o>>=1){
        ps  += __shfl_xor_sync(0xffffffffu, ps,  o);
        pss += __shfl_xor_sync(0xffffffffu, pss, o);
    }
    __shared__ float sS[8], sSS[8];
    if(lane==0){ sS[w] = ps; sSS[w] = pss; }
    __syncthreads();
    float S = 0.f, SS = 0.f;
    #pragma unroll
    for(int i=0;i<4;i++){ S += sS[rowl*4+i]; SS += sSS[rowl*4+i]; }
    float mu = S*(1.f/ND);
    float rs = rsqrtf(SS*(1.f/ND) - mu*mu + LN_EPS);
    float4 g4 = *(const float4*)&gw[e*ND + k];
    float4 b4 = *(const float4*)&bw[e*ND + k];
    float4 o4;
    o4.x = (s.x-mu)*rs*g4.x + b4.x;
    o4.y = (s.y-mu)*rs*g4.y + b4.y;
    o4.z = (s.z-mu)*rs*g4.z + b4.z;
    o4.w = (s.w-mu)*rs*g4.w + b4.w;
    *(float4*)&g_xo[base] = o4;
}

// ---------------- qt: fold Wk into query, 8 rows/block (+qdot on x==0) --------
__global__ void k_qt(const float* __restrict__ Wk, const float* __restrict__ bk){
    __shared__ float qh_s[NB*ND];   // 32KB, [b*512 + ((c + b) & 511)]
    __shared__ float wk_s[8*ND];    // 16KB, [r*512 + ((c + r*8) & 511)]
    int e = blockIdx.y, tid = threadIdx.x;
    int d0 = blockIdx.x*8;
    for(int i=tid; i<NB*ND; i+=256){
        int b = i >> 9, c = i & 511;
        qh_s[b*ND + ((c + b) & 511)] = g_qh[(b*NE+e)*ND + c];
    }
    for(int j=tid; j<8*128; j+=256){
        int r = j >> 7, c4 = (j & 127)*4;
        float4 v = *(const float4*)(Wk + ((size_t)(e*ND + d0 + r))*ND + c4);
        int base = r*ND, sw = r*8;
        wk_s[base + ((c4+0 + sw)&511)] = v.x;
        wk_s[base + ((c4+1 + sw)&511)] = v.y;
        wk_s[base + ((c4+2 + sw)&511)] = v.z;
        wk_s[base + ((c4+3 + sw)&511)] = v.w;
    }
    __syncthreads();
    if(blockIdx.x==0 && tid < NB*NH){
        int b = tid >> 3, h = tid & 7;
        float s = 0.f;
        const float* bp = bk + e*ND + h*64;
        #pragma unroll 8
        for(int cc=0; cc<64; cc++){
            int c = h*64 + cc;
            s += qh_s[b*ND + ((c + b)&511)] * bp[cc];
        }
        g_qdot[b*NEH + e*NH + h] = s*0.125f;
    }
    int h = tid >> 5, lane = tid & 31;
    int r4 = lane >> 3, bg = lane & 7;
    int b0 = bg*2;
    #pragma unroll
    for(int rr=0; rr<2; rr++){
        int row = rr*4 + r4;
        float a0 = 0.f, a1 = 0.f;
        #pragma unroll 8
        for(int c0=0; c0<64; c0++){
            int c = h*64 + c0;
            float w = wk_s[row*ND + ((c + row*8)&511)];
            a0 += w * qh_s[(b0  )*ND + ((c + b0  )&511)];
            a1 += w * qh_s[(b0+1)*ND + ((c + b0+1)&511)];
        }
        int d = d0 + row;
        g_qt[((size_t)(b0  )*NEH + e*NH + h)*ND + d] = a0*0.125f;
        g_qt[((size_t)(b0+1)*NEH + e*NH + h)*ND + d] = a1*0.125f;
    }
}

// ---- scores (tf32 mma): scores[b,eh,l] = qt[b,eh,:].R[b,l,:] + qdot ----
__global__ void k_scores(const float* __restrict__ R){
    __shared__ float As[64*36];
    __shared__ float Bs[128*36];
    int b = blockIdx.y, tid = threadIdx.x;
    int l0 = blockIdx.x*128;
    int w = tid >> 5, lane = tid & 31, g = lane >> 2, tr = lane & 3;
    const float* A  = g_qt + (size_t)b*NEH*ND;
    const float* Bg = R    + (size_t)b*NL*ND + (size_t)l0*ND;
    float acc[4][2][4];
    #pragma unroll
    for(int mi=0;mi<4;mi++)
        #pragma unroll
        for(int ni=0;ni<2;ni++)
            #pragma unroll
            for(int c=0;c<4;c++) acc[mi][ni][c] = 0.f;

    int ar = tid >> 2, ac = (tid & 3)*4;
    int brw = tid >> 1, bh = (tid & 1)*16;
    for(int kt=0; kt<ND; kt+=32){
        float4 va0 = *(const float4*)(A + (size_t)ar*ND + kt + ac);
        float4 va1 = *(const float4*)(A + (size_t)ar*ND + kt + 16 + ac);
        float* ap = As + ar*36;
        ap[ac   ]=tf32r(va0.x); ap[ac+1 ]=tf32r(va0.y); ap[ac+2 ]=tf32r(va0.z); ap[ac+3 ]=tf32r(va0.w);
        ap[ac+16]=tf32r(va1.x); ap[ac+17]=tf32r(va1.y); ap[ac+18]=tf32r(va1.z); ap[ac+19]=tf32r(va1.w);
        const float* brp = Bg + (size_t)brw*ND + kt + bh;
        float* bp = Bs + brw*36 + bh;
        #pragma unroll
        for(int q=0;q<4;q++){
            float4 v = *(const float4*)(brp + q*4);
            bp[q*4  ]=tf32r(v.x); bp[q*4+1]=tf32r(v.y); bp[q*4+2]=tf32r(v.z); bp[q*4+3]=tf32r(v.w);
        }
        __syncthreads();
        #pragma unroll
        for(int ks=0; ks<4; ks++){
            int k0 = ks*8;
            uint32_t af[4][4];
            #pragma unroll
            for(int mi=0;mi<4;mi++){
                af[mi][0] = __float_as_uint(As[(mi*16+g  )*36 + k0+tr  ]);
                af[mi][1] = __float_as_uint(As[(mi*16+g+8)*36 + k0+tr  ]);
                af[mi][2] = __float_as_uint(As[(mi*16+g  )*36 + k0+tr+4]);
                af[mi][3] = __float_as_uint(As[(mi*16+g+8)*36 + k0+tr+4]);
            }
            uint32_t bf[2][2];
            #pragma unroll
            for(int ni=0;ni<2;ni++){
                int n0 = w*16 + ni*8;
                bf[ni][0] = __float_as_uint(Bs[(n0+g)*36 + k0+tr  ]);
                bf[ni][1] = __float_as_uint(Bs[(n0+g)*36 + k0+tr+4]);
            }
            #pragma unroll
            for(int mi=0;mi<4;mi++)
                #pragma unroll
                for(int ni=0;ni<2;ni++)
                    mma_tf32(acc[mi][ni], af[mi][0],af[mi][1],af[mi][2],af[mi][3],
                             bf[ni][0], bf[ni][1]);
        }
        __syncthreads();
    }
    #pragma unroll
    for(int mi=0;mi<4;mi++){
        int ehA = mi*16+g, ehB = ehA+8;
        float qdA = g_qdot[b*NEH + ehA];
        float qdB = g_qdot[b*NEH + ehB];
        #pragma unroll
        for(int ni=0;ni<2;ni++){
            int lc = l0 + w*16 + ni*8 + tr*2;
            *(float2*)&g_probs[(size_t)(b*NEH+ehA)*NL + lc] =
                make_float2(acc[mi][ni][0]+qdA, acc[mi][ni][1]+qdA);
            *(float2*)&g_probs[(size_t)(b*NEH+ehB)*NL + lc] =
                make_float2(acc[mi][ni][2]+qdB, acc[mi][ni][3]+qdB);
        }
    }
}

// ---------------- softmax over l + entropy (fused) ----------------
__global__ void k_softent(){
    __shared__ float sump[NL];
    int be = blockIdx.x, tid = threadIdx.x;
    for(int i=tid; i<NL; i+=256) sump[i] = 0.f;
    __syncthreads();
    for(int h=0; h<NH; h++){
        float* p = g_probs + (size_t)(be*NH + h)*NL;
        float v[8];
        float m = -1e30f;
        #pragma unroll
        for(int i=0;i<8;i++){ v[i] = p[tid + i*256]; m = fmaxf(m, v[i]); }
        m = blkMax(m);
        float s = 0.f;
        #pragma unroll
        for(int i=0;i<8;i++){ v[i] = expf(v[i]-m); s += v[i]; }
        s = blkSum(s);
        float inv = 1.f/s;
        #pragma unroll
        for(int i=0;i<8;i++){
            float pv = v[i]*inv;
            p[tid + i*256] = pv;
            sump[tid + i*256] += pv;
        }
        __syncthreads();
    }
    float acc = 0.f;
    for(int i=tid; i<NL; i+=256){
        float sv = fmaxf(sump[i]*0.125f, 1e-12f);
        acc -= sv*logf(sv);
    }
    float Hent = blkSum(acc);
    if(tid==0) g_srel[be] = expf(-0.5f*Hent);
}

// ---- ctx (tf32 mma): ctxp[z][b,eh,d] = sum_{l in chunk z} probs*R ----
__global__ void k_ctx(const float* __restrict__ R){
    __shared__ float As[64*36];
    __shared__ float Bs[32*136];
    int b = blockIdx.y, z = blockIdx.z, tid = threadIdx.x;
    int d0 = blockIdx.x*128, lbase = z*512;
    int w = tid >> 5, lane = tid & 31, g = lane >> 2, tr = lane & 3;
    const float* A  = g_probs + (size_t)b*NEH*NL + lbase;
    const float* Bg = R       + (size_t)b*NL*ND + (size_t)lbase*ND + d0;
    float acc[4][2][4];
    #pragma unroll
    for(int mi=0;mi<4;mi++)
        #pragma unroll
        for(int ni=0;ni<2;ni++)
            #pragma unroll
            for(int c=0;c<4;c++) acc[mi][ni][c] = 0.f;

    int ar = tid >> 2, ac = (tid & 3)*4;
    int brw = tid >> 3, bseg = (tid & 7)*16;
    for(int kt=0; kt<512; kt+=32){
        float4 va0 = *(const float4*)(A + (size_t)ar*NL + kt + ac);
        float4 va1 = *(const float4*)(A + (size_t)ar*NL + kt + 16 + ac);
        float* ap = As + ar*36;
        ap[ac   ]=tf32r(va0.x); ap[ac+1 ]=tf32r(va0.y); ap[ac+2 ]=tf32r(va0.z); ap[ac+3 ]=tf32r(va0.w);
        ap[ac+16]=tf32r(va1.x); ap[ac+17]=tf32r(va1.y); ap[ac+18]=tf32r(va1.z); ap[ac+19]=tf32r(va1.w);
        const float* brp = Bg + (size_t)(kt+brw)*ND + bseg;
        float* bp = Bs + brw*136 + bseg;
        #pragma unroll
        for(int q=0;q<4;q++){
            float4 v = *(const float4*)(brp + q*4);
            bp[q*4  ]=tf32r(v.x); bp[q*4+1]=tf32r(v.y); bp[q*4+2]=tf32r(v.z); bp[q*4+3]=tf32r(v.w);
        }
        __syncthreads();
        #pragma unroll
        for(int ks=0; ks<4; ks++){
            int k0 = ks*8;
            uint32_t af[4][4];
            #pragma unroll
            for(int mi=0;mi<4;mi++){
                af[mi][0] = __float_as_uint(As[(mi*16+g  )*36 + k0+tr  ]);
                af[mi][1] = __float_as_uint(As[(mi*16+g+8)*36 + k0+tr  ]);
                af[mi][2] = __float_as_uint(As[(mi*16+g  )*36 + k0+tr+4]);
                af[mi][3] = __float_as_uint(As[(mi*16+g+8)*36 + k0+tr+4]);
            }
            uint32_t bf[2][2];
            #pragma unroll
            for(int ni=0;ni<2;ni++){
                int n0 = w*16 + ni*8;
                bf[ni][0] = __float_as_uint(Bs[(k0+tr  )*136 + n0+g]);
                bf[ni][1] = __float_as_uint(Bs[(k0+tr+4)*136 + n0+g]);
            }
            #pragma unroll
            for(int mi=0;mi<4;mi++)
                #pragma unroll
                for(int ni=0;ni<2;ni++)
                    mma_tf32(acc[mi][ni], af[mi][0],af[mi][1],af[mi][2],af[mi][3],
                             bf[ni][0], bf[ni][1]);
        }
        __syncthreads();
    }
    float* po = g_ctxp[z];
    #pragma unroll
    for(int mi=0;mi<4;mi++){
        int ehA = mi*16+g, ehB = ehA+8;
        #pragma unroll
        for(int ni=0;ni<2;ni++){
            int dc = d0 + w*16 + ni*8 + tr*2;
            *(float2*)&po[(size_t)(b*NEH+ehA)*ND + dc] =
                make_float2(acc[mi][ni][0], acc[mi][ni][1]);
            *(float2*)&po[(size_t)(b*NEH+ehB)*ND + dc] =
                make_float2(acc[mi][ni][2], acc[mi][ni][3]);
        }
    }
}

// ---- attnv: part[z][(b,e),j] = sum_{d in chunk} ctx[b,e8+h(j),d]*Wv[e,d,j] ----
__global__ void k_attnv(const float* __restrict__ Wv){
    int h = blockIdx.x, e = blockIdx.y, z = blockIdx.z, tid = threadIdx.x;
    __shared__ float xs[NB][129];
    for(int i=tid; i<NB*128; i+=256){
        int b = i >> 7, d = i & 127;
        size_t idx = ((size_t)(b*NEH + e*NH + h))*ND + z*128 + d;
        xs[b][d] = g_ctxp[0][idx] + g_ctxp[1][idx] + g_ctxp[2][idx] + g_ctxp[3][idx];
    }
    __syncthreads();
    int c4 = tid & 15, b = tid >> 4;
    int j = h*64 + c4*4;
    float4 a = {0,0,0,0};
    const float4* wp = (const float4*)(Wv + ((size_t)e*ND + z*128)*ND + j);
    #pragma unroll 8
    for(int d=0; d<128; d++){
        float4 w = wp[(size_t)d*(ND/4)];
        float x = xs[b][d];
        a.x += w.x*x; a.y += w.y*x; a.z += w.z*x; a.w += w.w*x;
    }
    float* po = g_part + (size_t)z*(NB*NE*ND);
    *(float4*)&po[((size_t)b*NE+e)*ND + j] = a;
}

// ---------------- final: gates (inline), gt, mixture, fused ----------------
__global__ void k_out(const float* __restrict__ q, const float* __restrict__ wg,
                      float* __restrict__ out){
    int b = blockIdx.x, tid = threadIdx.x;
    int w = tid >> 5, lane = tid & 31;
    __shared__ float lg[NE];
    float acc = 0.f;
    for(int d=lane; d<ND; d+=32) acc += q[b*ND+d] * wg[d*NE + w];
    #pragma unroll
    for(int o=16;o;o>>=1) acc += __shfl_xor_sync(0xffffffffu, acc, o);
    if(lane==0) lg[w] = acc;
    __syncthreads();
    __shared__ float gt[NE];
    if(tid==0){
        float m = -1e30f;
        #pragma unroll
        for(int e=0;e<NE;e++) m = fmaxf(m, lg[e]);
        float ex[NE], ssum = 0.f;
        #pragma unroll
        for(int e=0;e<NE;e++){ ex[e] = expf(lg[e]-m); ssum += ex[e]; }
        float s2 = 0.f, gg[NE];
        #pragma unroll
        for(int e=0;e<NE;e++){ gg[e] = (ex[e]/ssum)*g_srel[b*NE+e]; s2 += gg[e]; }
        float inv = 1.f/(s2 + 1e-9f);
        #pragma unroll
        for(int e=0;e<NE;e++){
            gt[e] = gg[e]*inv;
            out[NB*ND + NB*NE*ND + b*NE + e] = gt[e];
        }
    }
    __syncthreads();
    const float* y = out + NB*ND;
    #pragma unroll
    for(int it=0; it<2; it++){
        int d = tid + it*256;
        float mix = 0.f;
        #pragma unroll
        for(int e=0;e<NE;e++) mix += gt[e]*y[(size_t)(b*NE+e)*ND + d];
        out[b*ND + d] = mix;
    }
}

// ---------------- launch ----------------
extern "C" void kernel_launch(void* const* d_in, const int* in_sizes, int n_in,
                              void* d_out, int out_size) {
    const float* query  = (const float*)d_in[0];
    const float* retr   = (const float*)d_in[1];
    const float* w_gate = (const float*)d_in[2];
    const float* ln_q_g = (const float*)d_in[3];
    const float* ln_q_b = (const float*)d_in[4];
    const float* Wq     = (const float*)d_in[5];
    const float* bq     = (const float*)d_in[6];
    const float* Wk     = (const float*)d_in[7];
    const float* bk     = (const float*)d_in[8];
    const float* Wv     = (const float*)d_in[9];
    const float* bv     = (const float*)d_in[10];
    const float* Wo     = (const float*)d_in[11];
    const float* bo     = (const float*)d_in[12];
    const float* ln_o_g = (const float*)d_in[13];
    const float* ln_o_b = (const float*)d_in[14];
    const float* W1     = (const float*)d_in[15];
    const float* b1     = (const float*)d_in[16];
    const float* W2     = (const float*)d_in[17];
    const float* b2     = (const float*)d_in[18];
    float* out = (float*)d_out;

    float *p_qh, *p_attn, *p_x, *p_xo, *p_h1;
    cudaGetSymbolAddress((void**)&p_qh,   g_qh);
    cudaGetSymbolAddress((void**)&p_attn, g_attn);
    cudaGetSymbolAddress((void**)&p_x,    g_x);
    cudaGetSymbolAddress((void**)&p_xo,   g_xo);
    cudaGetSymbolAddress((void**)&p_h1,   g_h1);

    k_gstat  <<<NB, 256>>>(query);

    k_gemm<ND,ND,8,1> <<<dim3(2, NE, 8), 256>>>(Wq, query, ND, 0, ln_q_g, ln_q_b);
    k_redT<8,ND,9,0,0,0> <<<64, 256>>>(bq, nullptr, p_qh);

    k_qt     <<<dim3(64, NE), 256>>>(Wk, bk);

    k_scores <<<dim3(16, NB), 256>>>(retr);
    k_softent<<<NB*NE, 256>>>();
    k_ctx    <<<dim3(4, NB, 4), 256>>>(retr);

    k_attnv  <<<dim3(NH, NE, 4), 256>>>(Wv);
    k_redT<4,ND,9,0,0,0> <<<64, 256>>>(bv, nullptr, p_attn);

    k_gemm<ND,ND,8,0> <<<dim3(2, NE, 8), 256>>>(Wo, p_attn, NE*ND, ND, nullptr, nullptr);
    k_redln  <<<64, 256>>>(bo, query, ln_o_g, ln_o_b);

    k_gemm<NF,ND,2,0> <<<dim3(8, NE, 2), 256>>>(W1, p_xo, NE*ND, ND, nullptr, nullptr);
    k_redT<2,NF,11,0,1,1> <<<256, 256>>>(b1, nullptr, p_h1);

    k_gemm<ND,NF,8,0> <<<dim3(2, NE, 8), 256>>>(W2, p_h1, NF, NB*NF, nullptr, nullptr);
    k_redT<8,ND,9,2,0,0> <<<64, 256>>>(b2, p_x, out + NB*ND);

    k_out    <<<NB, 256>>>(query, w_gate, out);
}